// round 15
// baseline (speedup 1.0000x reference)
#include <cuda_runtime.h>
#include <cuda_bf16.h>
#include <cstdint>
#include <math.h>

#define BATCH 256
#define NNODE 512
#define FEAT  128
#define NE    4

// ---------------- scratch (static device allocs allowed) ----------------
__device__ __nv_bfloat16 g_wh[5 * FEAT * FEAT];                   // W hi [e][k][u] (slot 4 = W2)
__device__ __nv_bfloat16 g_wl[5 * FEAT * FEAT];                   // W lo
__device__ __nv_bfloat16 g_hh[(size_t)BATCH * NE * NNODE * FEAT]; // h hi [b][e][m][u]
__device__ __nv_bfloat16 g_hl[(size_t)BATCH * NE * NNODE * FEAT]; // h lo

// ---------------- helpers ----------------
__device__ __forceinline__ uint32_t smem_u32(const void* p) {
    uint32_t a;
    asm("{ .reg .u64 t; cvta.to.shared.u64 t, %1; cvt.u32.u64 %0, t; }" : "=r"(a) : "l"(p));
    return a;
}
#define SWZ(x)    ((x) ^ (((x) >> 3) & 0x70))   // 128B rows
#define SWZ256(x) ((x) ^ (((x) >> 4) & 0x70))   // 256B rows

__device__ __forceinline__ void split2(float a, float b, uint32_t& hh, uint32_t& ll) {
    __nv_bfloat162 h = __floats2bfloat162_rn(a, b);
    float ra = a - __low2float(h);
    float rb = b - __high2float(h);
    hh = *reinterpret_cast<uint32_t*>(&h);
    __nv_bfloat162 l = __floats2bfloat162_rn(ra, rb);
    ll = *reinterpret_cast<uint32_t*>(&l);
}

__device__ __forceinline__ void ldm4(uint32_t a[4], uint32_t adr) {
    asm volatile("ldmatrix.sync.aligned.m8n8.x4.shared.b16 {%0,%1,%2,%3}, [%4];"
        : "=r"(a[0]), "=r"(a[1]), "=r"(a[2]), "=r"(a[3]) : "r"(adr));
}
__device__ __forceinline__ void ldm4t(uint32_t a[4], uint32_t adr) {
    asm volatile("ldmatrix.sync.aligned.m8n8.x4.trans.shared.b16 {%0,%1,%2,%3}, [%4];"
        : "=r"(a[0]), "=r"(a[1]), "=r"(a[2]), "=r"(a[3]) : "r"(adr));
}
__device__ __forceinline__ void mma_bf(float c[4], const uint32_t a[4],
                                       uint32_t b0, uint32_t b1) {
    asm volatile("mma.sync.aligned.m16n8k16.row.col.f32.bf16.bf16.f32 "
        "{%0,%1,%2,%3}, {%4,%5,%6,%7}, {%8,%9}, {%0,%1,%2,%3};"
        : "+f"(c[0]), "+f"(c[1]), "+f"(c[2]), "+f"(c[3])
        : "r"(a[0]), "r"(a[1]), "r"(a[2]), "r"(a[3]), "r"(b0), "r"(b1));
}
#define CP_COMMIT() asm volatile("cp.async.commit_group;" ::: "memory")
#define CP_WAIT0()  asm volatile("cp.async.wait_group 0;" ::: "memory")
#define CPA16(dst, src) asm volatile("cp.async.cg.shared.global [%0], [%1], 16;" \
                                     :: "r"(dst), "l"(src) : "memory")

// ---- A tile: 128 rows x 128B [hi 64B | lo 64B], swizzled (per 32-k slab) ----
struct ARaw { float4 v[4]; };
__device__ __forceinline__ void loadA_raw(ARaw& a, const float* __restrict__ g, int rs, int t) {
    int r = t >> 1, c0 = (t & 1) * 16;
    const float* src = g + (size_t)r * rs + c0;
    #pragma unroll
    for (int j = 0; j < 4; j++) a.v[j] = *reinterpret_cast<const float4*>(src + 4 * j);
}
__device__ __forceinline__ void storeA_split(const ARaw& a, char* sm, int base, int t) {
    int r = t >> 1, c0 = (t & 1) * 16;
    #pragma unroll
    for (int j = 0; j < 4; j++) {
        uint32_t h0, l0, h1, l1;
        split2(a.v[j].x, a.v[j].y, h0, l0);
        split2(a.v[j].z, a.v[j].w, h1, l1);
        int col = c0 + 4 * j;
        *reinterpret_cast<uint2*>(sm + base + SWZ(r * 128 + col * 2)) = make_uint2(h0, h1);
        *reinterpret_cast<uint2*>(sm + base + SWZ(r * 128 + 64 + col * 2)) = make_uint2(l0, l1);
    }
}

// ---- B tile (k_mp): [32 k rows][128 u] per plane; row stride FEAT (h rows AND W rows) ----
__device__ __forceinline__ void loadB32_async(uint32_t sb, int base,
                                              const __nv_bfloat16* __restrict__ gh,
                                              const __nv_bfloat16* __restrict__ gl, int t) {
    #pragma unroll
    for (int j = 0; j < 4; j++) {
        int c = t + 256 * j;
        int p = c >> 9, kr = (c >> 4) & 31, ch = c & 15;
        const __nv_bfloat16* src = (p ? gl : gh) + (size_t)kr * FEAT + ch * 8;
        uint32_t dst = sb + base + p * 8192 + SWZ256(kr * 256 + ch * 16);
        CPA16(dst, src);
    }
}
// ---- B tile (k_lin W): [128 k rows][128 u] per plane, 256B rows, SWZ256 ----
__device__ __forceinline__ void loadB128_async(uint32_t sb, int base,
                                               const __nv_bfloat16* __restrict__ gh,
                                               const __nv_bfloat16* __restrict__ gl, int t) {
    #pragma unroll
    for (int j = 0; j < 8; j++) {
        int c = t + 256 * j;
        int kr = c >> 4, ch = c & 15;
        CPA16(sb + base + SWZ256(kr * 256 + ch * 16), gh + (size_t)kr * FEAT + ch * 8);
        CPA16(sb + base + 32768 + SWZ256(kr * 256 + ch * 16), gl + (size_t)kr * FEAT + ch * 8);
    }
}

// ---- compute one 32-k stage (warp tile 32x64, 3 split-products) ----
__device__ __forceinline__ void compute_stage(uint32_t sb, int offA, int offB,
                                              int kbase, int pstride,
                                              int wm, int wn, int lane,
                                              float acc[2][8][4]) {
    #pragma unroll
    for (int ks = 0; ks < 2; ks++) {
        uint32_t Ah[2][4], Al[2][4];
        #pragma unroll
        for (int mf = 0; mf < 2; mf++) {
            int row = wm * 32 + mf * 16 + (lane & 15);
            int kk  = ks * 16 + ((lane >> 4) * 8);
            ldm4(Ah[mf], sb + offA + SWZ(row * 128 + kk * 2));
            ldm4(Al[mf], sb + offA + SWZ(row * 128 + 64 + kk * 2));
        }
        int krow  = kbase + ks * 16 + ((lane >> 3) & 1) * 8 + (lane & 7);
        int cbase = wn * 8 + (lane >> 4);
        #pragma unroll
        for (int nfp = 0; nfp < 4; nfp++) {
            uint32_t bofs = SWZ256(krow * 256 + (cbase + nfp * 2) * 16);
            uint32_t BH[4], BL[4];
            ldm4t(BH, sb + offB + bofs);
            ldm4t(BL, sb + offB + pstride + bofs);
            int n0 = nfp * 2, n1 = nfp * 2 + 1;
            mma_bf(acc[0][n0], Ah[0], BH[0], BH[1]);
            mma_bf(acc[1][n0], Ah[1], BH[0], BH[1]);
            mma_bf(acc[0][n0], Ah[0], BL[0], BL[1]);
            mma_bf(acc[1][n0], Ah[1], BL[0], BL[1]);
            mma_bf(acc[0][n0], Al[0], BH[0], BH[1]);
            mma_bf(acc[1][n0], Al[1], BH[0], BH[1]);
            mma_bf(acc[0][n1], Ah[0], BH[2], BH[3]);
            mma_bf(acc[1][n1], Ah[1], BH[2], BH[3]);
            mma_bf(acc[0][n1], Ah[0], BL[2], BL[3]);
            mma_bf(acc[1][n1], Ah[1], BL[2], BL[3]);
            mma_bf(acc[0][n1], Al[0], BH[2], BH[3]);
            mma_bf(acc[1][n1], Al[1], BH[2], BH[3]);
        }
    }
}

// ---------------- pre-kernel: split W (slots 0..3 = W_adj, 4 = W2) ----------------
__global__ __launch_bounds__(256) void k_split_w(const float* __restrict__ Wadj,
                                                 const float* __restrict__ W2) {
    int idx4 = blockIdx.x * 256 + threadIdx.x;
    int e = idx4 >> 12;
    const float* src = (e < NE) ? (Wadj + (size_t)idx4 * 4)
                                : (W2 + ((size_t)idx4 - 4 * 4096) * 4);
    float4 v = *reinterpret_cast<const float4*>(src);
    uint32_t h0, l0, h1, l1;
    split2(v.x, v.y, h0, l0);
    split2(v.z, v.w, h1, l1);
    *reinterpret_cast<uint2*>(g_wh + (size_t)idx4 * 4) = make_uint2(h0, h1);
    *reinterpret_cast<uint2*>(g_wl + (size_t)idx4 * 4) = make_uint2(l0, l1);
}

// ---------------- k_lin: h_e = n @ W_e + b_e, e = 0..3 only ----------------
#define LIN_SMEM 196608
__global__ __launch_bounds__(256, 1) void k_lin(const float* __restrict__ nt,
                                                const float* __restrict__ badj) {
    extern __shared__ char sm[];
    uint32_t sb = smem_u32(sm);
    int t = threadIdx.x, lane = t & 31, w = t >> 5;
    int wm = w >> 1, wn = w & 1;
    int r0 = blockIdx.x * 128;
    int b = r0 >> 9, m0 = r0 & 511;

    loadB128_async(sb, 65536, g_wh, g_wl, t);
    CP_COMMIT();
    #pragma unroll
    for (int st = 0; st < 4; st++) {
        ARaw a;
        loadA_raw(a, nt + (size_t)r0 * FEAT + st * 32, FEAT, t);
        storeA_split(a, sm, st * 16384, t);
    }
    CP_WAIT0();
    __syncthreads();

    #pragma unroll 1
    for (int e = 0; e < NE; e++) {
        int buf = e & 1;
        if (e < NE - 1) {
            loadB128_async(sb, 65536 + (buf ^ 1) * 65536,
                           g_wh + (size_t)(e + 1) * FEAT * FEAT,
                           g_wl + (size_t)(e + 1) * FEAT * FEAT, t);
            CP_COMMIT();
        }

        float acc[2][8][4];
        #pragma unroll
        for (int i = 0; i < 2; i++)
            #pragma unroll
            for (int j = 0; j < 8; j++)
                #pragma unroll
                for (int q = 0; q < 4; q++) acc[i][j][q] = 0.f;

        #pragma unroll
        for (int st = 0; st < 4; st++)
            compute_stage(sb, st * 16384, 65536 + buf * 65536, st * 32, 32768,
                          wm, wn, lane, acc);

        const float* bias = badj + e * FEAT;
        #pragma unroll
        for (int mf = 0; mf < 2; mf++)
            #pragma unroll
            for (int nf = 0; nf < 8; nf++) {
                int r = wm * 32 + mf * 16 + (lane >> 2);
                int c = wn * 64 + nf * 8 + 2 * (lane & 3);
                float2 bv = *reinterpret_cast<const float2*>(bias + c);
                float h0 = acc[mf][nf][0] + bv.x, h1 = acc[mf][nf][1] + bv.y;
                float h2 = acc[mf][nf][2] + bv.x, h3 = acc[mf][nf][3] + bv.y;
                size_t g0 = ((size_t)(b * NE + e) * NNODE + m0 + r) * FEAT + c;
                size_t g1 = g0 + (size_t)8 * FEAT;
                uint32_t hh, ll;
                split2(h0, h1, hh, ll);
                *reinterpret_cast<uint32_t*>(g_hh + g0) = hh;
                *reinterpret_cast<uint32_t*>(g_hl + g0) = ll;
                split2(h2, h3, hh, ll);
                *reinterpret_cast<uint32_t*>(g_hh + g1) = hh;
                *reinterpret_cast<uint32_t*>(g_hl + g1) = ll;
            }
        if (e < NE - 1) {
            CP_WAIT0();
            __syncthreads();
        }
    }
}

// ---------------- k_mp: out = tanh(n@W2 + b2 + sum_e adj_e @ h_e) ----------------
// 68 chunks: 0..3 = n@W2 (A = n rows fp32-split, B = W2 hi/lo); 4..67 = adjacency.
// smem: A bufs @ s*16384 (32KB); B bufs @ 32768 + s*16384 (hi 8KB | lo 8KB). 64KB.
#define MP_SMEM 65536
__global__ __launch_bounds__(256, 2) void k_mp(const float* __restrict__ adj,
                                               const float* __restrict__ nt,
                                               const float* __restrict__ b2,
                                               float* __restrict__ out) {
    extern __shared__ char sm[];
    uint32_t sb = smem_u32(sm);
    int t = threadIdx.x, lane = t & 31, w = t >> 5;
    int wm = w >> 1, wn = w & 1;
    int b = blockIdx.x >> 2, n0 = (blockIdx.x & 3) * 128;

    const __nv_bfloat16* w2h = g_wh + (size_t)NE * FEAT * FEAT;
    const __nv_bfloat16* w2l = g_wl + (size_t)NE * FEAT * FEAT;
    const float* nrow = nt + ((size_t)b * NNODE + n0) * FEAT;   // this block's n rows

    float acc[2][8][4];
    #pragma unroll
    for (int i = 0; i < 2; i++)
        #pragma unroll
        for (int j = 0; j < 8; j++)
            #pragma unroll
            for (int q = 0; q < 4; q++) acc[i][j][q] = 0.f;

    ARaw ar;
    // prologue: chunk 0 = n@W2 k[0:32)
    {
        loadA_raw(ar, nrow, FEAT, t);
        loadB32_async(sb, 32768, w2h, w2l, t);
        CP_COMMIT();
        storeA_split(ar, sm, 0, t);
        CP_WAIT0();
        __syncthreads();
    }

    // chunk i: i<4 -> lin2 (k0=i*32); else j=i-4: e=j>>4, k0=(j&15)*32
    #pragma unroll 1
    for (int i = 0; i < 68; i++) {
        int s = i & 1;
        if (i < 67) {
            int nx = i + 1;
            const float* Ap;
            const __nv_bfloat16 *Bh, *Bl;
            int ars;
            if (nx < 4) {
                int k0 = nx * 32;
                Ap = nrow + k0;          ars = FEAT;
                Bh = w2h + (size_t)k0 * FEAT;
                Bl = w2l + (size_t)k0 * FEAT;
            } else {
                int j = nx - 4, e = j >> 4, k0 = (j & 15) * 32;
                Ap = adj + ((size_t)(b * NE + e) * NNODE + n0) * NNODE + k0;
                ars = NNODE;
                size_t hb = ((size_t)(b * NE + e) * NNODE + k0) * FEAT;
                Bh = g_hh + hb;
                Bl = g_hl + hb;
            }
            loadA_raw(ar, Ap, ars, t);   // LDGs issued; split deferred past compute
            loadB32_async(sb, 32768 + (s ^ 1) * 16384, Bh, Bl, t);
            CP_COMMIT();
        }
        compute_stage(sb, s * 16384, 32768 + s * 16384, 0, 8192, wm, wn, lane, acc);
        if (i < 67) {
            __syncthreads();
            storeA_split(ar, sm, (s ^ 1) * 16384, t);
            CP_WAIT0();
            __syncthreads();
        }
    }

    // fused epilogue: + b2, tanh, store
    #pragma unroll
    for (int mf = 0; mf < 2; mf++)
        #pragma unroll
        for (int nf = 0; nf < 8; nf++) {
            int r = wm * 32 + mf * 16 + (lane >> 2);
            int c = wn * 64 + nf * 8 + 2 * (lane & 3);
            float2 bv = *reinterpret_cast<const float2*>(b2 + c);
            size_t g0 = ((size_t)b * NNODE + n0 + r) * FEAT + c;
            *reinterpret_cast<float2*>(out + g0) =
                make_float2(tanhf(acc[mf][nf][0] + bv.x), tanhf(acc[mf][nf][1] + bv.y));
            size_t g1 = g0 + (size_t)8 * FEAT;
            *reinterpret_cast<float2*>(out + g1) =
                make_float2(tanhf(acc[mf][nf][2] + bv.x), tanhf(acc[mf][nf][3] + bv.y));
        }
}

// ---------------- launch ----------------
extern "C" void kernel_launch(void* const* d_in, const int* in_sizes, int n_in,
                              void* d_out, int out_size)
{
    const float* n_tensor   = (const float*)d_in[0];
    const float* adj_tensor = (const float*)d_in[1];
    const float* W_adj      = (const float*)d_in[2];
    const float* b_adj      = (const float*)d_in[3];
    const float* W2         = (const float*)d_in[4];
    const float* b2         = (const float*)d_in[5];
    float* out = (float*)d_out;

    cudaFuncSetAttribute(k_lin, cudaFuncAttributeMaxDynamicSharedMemorySize, LIN_SMEM);
    cudaFuncSetAttribute(k_mp,  cudaFuncAttributeMaxDynamicSharedMemorySize, MP_SMEM);

    k_split_w<<<80, 256>>>(W_adj, W2);
    k_lin<<<(BATCH * NNODE) / 128, 256, LIN_SMEM>>>(n_tensor, b_adj);
    k_mp<<<BATCH * 4, 256, MP_SMEM>>>(adj_tensor, n_tensor, b2, out);
}

// round 16
// speedup vs baseline: 1.0135x; 1.0135x over previous
#include <cuda_runtime.h>
#include <cuda_bf16.h>
#include <cstdint>
#include <math.h>

#define BATCH 256
#define NNODE 512
#define FEAT  128
#define NE    4

// ---------------- scratch (static device allocs allowed) ----------------
__device__ __nv_bfloat16 g_wh[5 * FEAT * FEAT];                   // W hi [e][k][u]
__device__ __nv_bfloat16 g_wl[5 * FEAT * FEAT];                   // W lo
__device__ __nv_bfloat16 g_hh[(size_t)BATCH * NE * NNODE * FEAT]; // h hi [b][e][m][u]
__device__ __nv_bfloat16 g_hl[(size_t)BATCH * NE * NNODE * FEAT]; // h lo
__device__ float         g_l2[(size_t)BATCH * NNODE * FEAT];      // n@W2+b2 [row][u]

// ---------------- helpers ----------------
__device__ __forceinline__ uint32_t smem_u32(const void* p) {
    uint32_t a;
    asm("{ .reg .u64 t; cvta.to.shared.u64 t, %1; cvt.u32.u64 %0, t; }" : "=r"(a) : "l"(p));
    return a;
}
#define SWZ(x)    ((x) ^ (((x) >> 3) & 0x70))   // 128B rows
#define SWZ256(x) ((x) ^ (((x) >> 4) & 0x70))   // 256B rows

__device__ __forceinline__ void split2(float a, float b, uint32_t& hh, uint32_t& ll) {
    __nv_bfloat162 h = __floats2bfloat162_rn(a, b);
    float ra = a - __low2float(h);
    float rb = b - __high2float(h);
    hh = *reinterpret_cast<uint32_t*>(&h);
    __nv_bfloat162 l = __floats2bfloat162_rn(ra, rb);
    ll = *reinterpret_cast<uint32_t*>(&l);
}

__device__ __forceinline__ void ldm4(uint32_t a[4], uint32_t adr) {
    asm volatile("ldmatrix.sync.aligned.m8n8.x4.shared.b16 {%0,%1,%2,%3}, [%4];"
        : "=r"(a[0]), "=r"(a[1]), "=r"(a[2]), "=r"(a[3]) : "r"(adr));
}
__device__ __forceinline__ void ldm4t(uint32_t a[4], uint32_t adr) {
    asm volatile("ldmatrix.sync.aligned.m8n8.x4.trans.shared.b16 {%0,%1,%2,%3}, [%4];"
        : "=r"(a[0]), "=r"(a[1]), "=r"(a[2]), "=r"(a[3]) : "r"(adr));
}
__device__ __forceinline__ void mma_bf(float c[4], const uint32_t a[4],
                                       uint32_t b0, uint32_t b1) {
    asm volatile("mma.sync.aligned.m16n8k16.row.col.f32.bf16.bf16.f32 "
        "{%0,%1,%2,%3}, {%4,%5,%6,%7}, {%8,%9}, {%0,%1,%2,%3};"
        : "+f"(c[0]), "+f"(c[1]), "+f"(c[2]), "+f"(c[3])
        : "r"(a[0]), "r"(a[1]), "r"(a[2]), "r"(a[3]), "r"(b0), "r"(b1));
}
#define CP_COMMIT() asm volatile("cp.async.commit_group;" ::: "memory")
#define CP_WAIT0()  asm volatile("cp.async.wait_group 0;" ::: "memory")
#define CPA16(dst, src) asm volatile("cp.async.cg.shared.global [%0], [%1], 16;" \
                                     :: "r"(dst), "l"(src) : "memory")

// ---- A tile: 128 rows x 128B [hi 64B | lo 64B], swizzled (per 32-k slab) ----
struct ARaw { float4 v[4]; };
__device__ __forceinline__ void loadA_raw(ARaw& a, const float* __restrict__ g, int rs, int t) {
    int r = t >> 1, c0 = (t & 1) * 16;
    const float* src = g + (size_t)r * rs + c0;
    #pragma unroll
    for (int j = 0; j < 4; j++) a.v[j] = *reinterpret_cast<const float4*>(src + 4 * j);
}
__device__ __forceinline__ void storeA_split(const ARaw& a, char* sm, int base, int t) {
    int r = t >> 1, c0 = (t & 1) * 16;
    #pragma unroll
    for (int j = 0; j < 4; j++) {
        uint32_t h0, l0, h1, l1;
        split2(a.v[j].x, a.v[j].y, h0, l0);
        split2(a.v[j].z, a.v[j].w, h1, l1);
        int col = c0 + 4 * j;
        *reinterpret_cast<uint2*>(sm + base + SWZ(r * 128 + col * 2)) = make_uint2(h0, h1);
        *reinterpret_cast<uint2*>(sm + base + SWZ(r * 128 + 64 + col * 2)) = make_uint2(l0, l1);
    }
}

// ---- B tile (k_mp): [32 k rows][128 u] per plane (row-major h) ----
__device__ __forceinline__ void loadB32_async(uint32_t sb, int base,
                                              const __nv_bfloat16* __restrict__ gh,
                                              const __nv_bfloat16* __restrict__ gl, int t) {
    #pragma unroll
    for (int j = 0; j < 4; j++) {
        int c = t + 256 * j;
        int p = c >> 9, kr = (c >> 4) & 31, ch = c & 15;
        const __nv_bfloat16* src = (p ? gl : gh) + (size_t)kr * FEAT + ch * 8;
        uint32_t dst = sb + base + p * 8192 + SWZ256(kr * 256 + ch * 16);
        CPA16(dst, src);
    }
}
// ---- B tile (k_lin W): [128 k rows][128 u] per plane, 256B rows, SWZ256 ----
__device__ __forceinline__ void loadB128_async(uint32_t sb, int base,
                                               const __nv_bfloat16* __restrict__ gh,
                                               const __nv_bfloat16* __restrict__ gl, int t) {
    #pragma unroll
    for (int j = 0; j < 8; j++) {
        int c = t + 256 * j;
        int kr = c >> 4, ch = c & 15;
        CPA16(sb + base + SWZ256(kr * 256 + ch * 16), gh + (size_t)kr * FEAT + ch * 8);
        CPA16(sb + base + 32768 + SWZ256(kr * 256 + ch * 16), gl + (size_t)kr * FEAT + ch * 8);
    }
}

// ---- compute one 32-k stage (warp tile 32x64) ----
__device__ __forceinline__ void compute_stage(uint32_t sb, int offA, int offB,
                                              int kbase, int pstride,
                                              int wm, int wn, int lane,
                                              float acc[2][8][4]) {
    #pragma unroll
    for (int ks = 0; ks < 2; ks++) {
        uint32_t Ah[2][4], Al[2][4];
        #pragma unroll
        for (int mf = 0; mf < 2; mf++) {
            int row = wm * 32 + mf * 16 + (lane & 15);
            int kk  = ks * 16 + ((lane >> 4) * 8);
            ldm4(Ah[mf], sb + offA + SWZ(row * 128 + kk * 2));
            ldm4(Al[mf], sb + offA + SWZ(row * 128 + 64 + kk * 2));
        }
        int krow  = kbase + ks * 16 + ((lane >> 3) & 1) * 8 + (lane & 7);
        int cbase = wn * 8 + (lane >> 4);
        #pragma unroll
        for (int nfp = 0; nfp < 4; nfp++) {
            uint32_t bofs = SWZ256(krow * 256 + (cbase + nfp * 2) * 16);
            uint32_t BH[4], BL[4];
            ldm4t(BH, sb + offB + bofs);
            ldm4t(BL, sb + offB + pstride + bofs);
            int n0 = nfp * 2, n1 = nfp * 2 + 1;
            mma_bf(acc[0][n0], Ah[0], BH[0], BH[1]);
            mma_bf(acc[1][n0], Ah[1], BH[0], BH[1]);
            mma_bf(acc[0][n0], Ah[0], BL[0], BL[1]);
            mma_bf(acc[1][n0], Ah[1], BL[0], BL[1]);
            mma_bf(acc[0][n0], Al[0], BH[0], BH[1]);
            mma_bf(acc[1][n0], Al[1], BH[0], BH[1]);
            mma_bf(acc[0][n1], Ah[0], BH[2], BH[3]);
            mma_bf(acc[1][n1], Ah[1], BH[2], BH[3]);
            mma_bf(acc[0][n1], Ah[0], BL[2], BL[3]);
            mma_bf(acc[1][n1], Ah[1], BL[2], BL[3]);
            mma_bf(acc[0][n1], Al[0], BH[2], BH[3]);
            mma_bf(acc[1][n1], Al[1], BH[2], BH[3]);
        }
    }
}

// ---------------- pre-kernel: split W ----------------
__global__ __launch_bounds__(256) void k_split_w(const float* __restrict__ Wadj,
                                                 const float* __restrict__ W2) {
    int idx4 = blockIdx.x * 256 + threadIdx.x;
    int e = idx4 >> 12;
    const float* src = (e < NE) ? (Wadj + (size_t)idx4 * 4)
                                : (W2 + ((size_t)idx4 - 4 * 4096) * 4);
    float4 v = *reinterpret_cast<const float4*>(src);
    uint32_t h0, l0, h1, l1;
    split2(v.x, v.y, h0, l0);
    split2(v.z, v.w, h1, l1);
    *reinterpret_cast<uint2*>(g_wh + (size_t)idx4 * 4) = make_uint2(h0, h1);
    *reinterpret_cast<uint2*>(g_wl + (size_t)idx4 * 4) = make_uint2(l0, l1);
}

// ---------------- k_lin: h_e = n @ W_e + b_e, loop e in-block ----------------
#define LIN_SMEM 196608
__global__ __launch_bounds__(256, 1) void k_lin(const float* __restrict__ nt,
                                                const float* __restrict__ badj,
                                                const float* __restrict__ b2) {
    extern __shared__ char sm[];
    uint32_t sb = smem_u32(sm);
    int t = threadIdx.x, lane = t & 31, w = t >> 5;
    int wm = w >> 1, wn = w & 1;
    int r0 = blockIdx.x * 128;
    int b = r0 >> 9, m0 = r0 & 511;

    loadB128_async(sb, 65536, g_wh, g_wl, t);
    CP_COMMIT();
    #pragma unroll
    for (int st = 0; st < 4; st++) {
        ARaw a;
        loadA_raw(a, nt + (size_t)r0 * FEAT + st * 32, FEAT, t);
        storeA_split(a, sm, st * 16384, t);
    }
    CP_WAIT0();
    __syncthreads();

    #pragma unroll 1
    for (int e = 0; e <= NE; e++) {
        int buf = e & 1;
        if (e < NE) {
            loadB128_async(sb, 65536 + (buf ^ 1) * 65536,
                           g_wh + (size_t)(e + 1) * FEAT * FEAT,
                           g_wl + (size_t)(e + 1) * FEAT * FEAT, t);
            CP_COMMIT();
        }

        float acc[2][8][4];
        #pragma unroll
        for (int i = 0; i < 2; i++)
            #pragma unroll
            for (int j = 0; j < 8; j++)
                #pragma unroll
                for (int q = 0; q < 4; q++) acc[i][j][q] = 0.f;

        #pragma unroll
        for (int st = 0; st < 4; st++)
            compute_stage(sb, st * 16384, 65536 + buf * 65536, st * 32, 32768,
                          wm, wn, lane, acc);

        const float* bias = (e < NE) ? (badj + e * FEAT) : b2;
        #pragma unroll
        for (int mf = 0; mf < 2; mf++)
            #pragma unroll
            for (int nf = 0; nf < 8; nf++) {
                int r = wm * 32 + mf * 16 + (lane >> 2);
                int c = wn * 64 + nf * 8 + 2 * (lane & 3);
                float2 bv = *reinterpret_cast<const float2*>(bias + c);
                float h0 = acc[mf][nf][0] + bv.x, h1 = acc[mf][nf][1] + bv.y;
                float h2 = acc[mf][nf][2] + bv.x, h3 = acc[mf][nf][3] + bv.y;
                if (e < NE) {
                    size_t g0 = ((size_t)(b * NE + e) * NNODE + m0 + r) * FEAT + c;
                    size_t g1 = g0 + (size_t)8 * FEAT;
                    uint32_t hh, ll;
                    split2(h0, h1, hh, ll);
                    *reinterpret_cast<uint32_t*>(g_hh + g0) = hh;
                    *reinterpret_cast<uint32_t*>(g_hl + g0) = ll;
                    split2(h2, h3, hh, ll);
                    *reinterpret_cast<uint32_t*>(g_hh + g1) = hh;
                    *reinterpret_cast<uint32_t*>(g_hl + g1) = ll;
                } else {
                    size_t g0 = (size_t)(r0 + r) * FEAT + c;
                    *reinterpret_cast<float2*>(g_l2 + g0) = make_float2(h0, h1);
                    *reinterpret_cast<float2*>(g_l2 + g0 + (size_t)8 * FEAT) =
                        make_float2(h2, h3);
                }
            }
        if (e < NE) {
            CP_WAIT0();
            __syncthreads();
        }
    }
}

// ---------------- k_mp: out = tanh(sum_e adj_e @ h_e + lin2) ----------------
// smem: A bufs @ s*16384 (32KB); B bufs @ 32768 + s*16384 (hi 8KB | lo 8KB). 64KB.
#define MP_SMEM 65536
__global__ __launch_bounds__(256, 2) void k_mp(const float* __restrict__ adj,
                                               float* __restrict__ out) {
    extern __shared__ char sm[];
    uint32_t sb = smem_u32(sm);
    int t = threadIdx.x, lane = t & 31, w = t >> 5;
    int wm = w >> 1, wn = w & 1;
    int b = blockIdx.x >> 2, n0 = (blockIdx.x & 3) * 128;

    float acc[2][8][4];
    #pragma unroll
    for (int i = 0; i < 2; i++)
        #pragma unroll
        for (int j = 0; j < 8; j++)
            #pragma unroll
            for (int q = 0; q < 4; q++) acc[i][j][q] = 0.f;

    ARaw ar;
    // chunk i: e = i>>4, k0 = (i&15)*32
    {
        const float* Ap = adj + ((size_t)(b * NE) * NNODE + n0) * NNODE;
        loadA_raw(ar, Ap, NNODE, t);
        size_t hb = (size_t)(b * NE) * NNODE * FEAT;
        loadB32_async(sb, 32768, g_hh + hb, g_hl + hb, t);
        CP_COMMIT();
        storeA_split(ar, sm, 0, t);
        CP_WAIT0();
        __syncthreads();
    }

    #pragma unroll 1
    for (int i = 0; i < 64; i++) {
        int s = i & 1;
        if (i < 63) {
            int e = (i + 1) >> 4, k0 = ((i + 1) & 15) * 32;
            const float* Ap = adj + ((size_t)(b * NE + e) * NNODE + n0) * NNODE + k0;
            loadA_raw(ar, Ap, NNODE, t);   // LDGs issued; split deferred past compute
            size_t hb = ((size_t)(b * NE + e) * NNODE + k0) * FEAT;
            loadB32_async(sb, 32768 + (s ^ 1) * 16384, g_hh + hb, g_hl + hb, t);
            CP_COMMIT();
        }
        compute_stage(sb, s * 16384, 32768 + s * 16384, 0, 8192, wm, wn, lane, acc);
        if (i < 63) {
            __syncthreads();
            storeA_split(ar, sm, (s ^ 1) * 16384, t);
            CP_WAIT0();
            __syncthreads();
        }
    }

    // fused epilogue from fragments
    #pragma unroll
    for (int mf = 0; mf < 2; mf++)
        #pragma unroll
        for (int nf = 0; nf < 8; nf++) {
            int r = wm * 32 + mf * 16 + (lane >> 2);
            int c = wn * 64 + nf * 8 + 2 * (lane & 3);
            size_t g0 = ((size_t)b * NNODE + n0 + r) * FEAT + c;
            float2 lv0 = *reinterpret_cast<const float2*>(g_l2 + g0);
            *reinterpret_cast<float2*>(out + g0) =
                make_float2(tanhf(acc[mf][nf][0] + lv0.x), tanhf(acc[mf][nf][1] + lv0.y));
            size_t g1 = g0 + (size_t)8 * FEAT;
            float2 lv1 = *reinterpret_cast<const float2*>(g_l2 + g1);
            *reinterpret_cast<float2*>(out + g1) =
                make_float2(tanhf(acc[mf][nf][2] + lv1.x), tanhf(acc[mf][nf][3] + lv1.y));
        }
}

// ---------------- launch ----------------
extern "C" void kernel_launch(void* const* d_in, const int* in_sizes, int n_in,
                              void* d_out, int out_size)
{
    const float* n_tensor   = (const float*)d_in[0];
    const float* adj_tensor = (const float*)d_in[1];
    const float* W_adj      = (const float*)d_in[2];
    const float* b_adj      = (const float*)d_in[3];
    const float* W2         = (const float*)d_in[4];
    const float* b2         = (const float*)d_in[5];
    float* out = (float*)d_out;

    cudaFuncSetAttribute(k_lin, cudaFuncAttributeMaxDynamicSharedMemorySize, LIN_SMEM);
    cudaFuncSetAttribute(k_mp,  cudaFuncAttributeMaxDynamicSharedMemorySize, MP_SMEM);

    k_split_w<<<80, 256>>>(W_adj, W2);
    k_lin<<<(BATCH * NNODE) / 128, 256, LIN_SMEM>>>(n_tensor, b_adj, b2);
    k_mp<<<BATCH * 4, 256, MP_SMEM>>>(adj_tensor, out);
}